// round 17
// baseline (speedup 1.0000x reference)
#include <cuda_runtime.h>
#include <cstdint>
#include <cstddef>

#define HID 512
#define TT  1024
#define NB  128
#define RTOT (NB*TT)

typedef unsigned long long u64;

// ping-pong activation buffers (xp in / ys out, in place), 256 MB each
__device__ float g_bufA[(size_t)RTOT * HID];
__device__ float g_bufB[(size_t)RTOT * HID];

// ---------------- helpers ----------------
__device__ __forceinline__ uint32_t smem_u32(const void* p) {
    return (uint32_t)__cvta_generic_to_shared(p);
}
__device__ __forceinline__ uint32_t mapa_u32(uint32_t addr, uint32_t rank) {
    uint32_t r;
    asm("mapa.shared::cluster.u32 %0, %1, %2;" : "=r"(r) : "r"(addr), "r"(rank));
    return r;
}
__device__ __forceinline__ void cluster_sync_all() {
    asm volatile("barrier.cluster.arrive.aligned;" ::: "memory");
    asm volatile("barrier.cluster.wait.aligned;" ::: "memory");
}
__device__ __forceinline__ uint32_t ctarank() {
    uint32_t r; asm("mov.u32 %0, %%cluster_ctarank;" : "=r"(r)); return r;
}
__device__ __forceinline__ void mbar_init(uint32_t addr, uint32_t cnt) {
    asm volatile("mbarrier.init.shared.b64 [%0], %1;" :: "r"(addr), "r"(cnt) : "memory");
}
// consumer-side: arrive + declare expected transaction bytes for this phase
__device__ __forceinline__ void mbar_expect(uint32_t addr, uint32_t bytes) {
    asm volatile("mbarrier.arrive.expect_tx.shared.b64 _, [%0], %1;"
                 :: "r"(addr), "r"(bytes) : "memory");
}
// bulk smem->peer-smem copy, completion counted (bytes) on the peer's mbarrier
__device__ __forceinline__ void bulk_copy_cluster(uint32_t dst, uint32_t src,
                                                  uint32_t bytes, uint32_t mbar) {
    asm volatile("cp.async.bulk.shared::cluster.shared::cta.mbarrier::complete_tx::bytes "
                 "[%0], [%1], %2, [%3];"
                 :: "r"(dst), "r"(src), "r"(bytes), "r"(mbar) : "memory");
}
__device__ __forceinline__ void fence_proxy_async_shared() {
    asm volatile("fence.proxy.async.shared::cta;" ::: "memory");
}
__device__ __forceinline__ void mbar_wait(uint32_t addr, uint32_t parity) {
    asm volatile(
        "{\n\t.reg .pred P;\n"
        "WAIT_%=:\n\t"
        "mbarrier.try_wait.parity.acquire.cluster.shared::cta.b64 P, [%0], %1, 0x989680;\n\t"
        "@!P bra WAIT_%=;\n\t}"
        :: "r"(addr), "r"(parity) : "memory");
}
// accurate tanh, immune to --use_fast_math's tanh.approx
__device__ __forceinline__ float my_tanh(float x) {
    float e = __expf(2.0f * x);
    return 1.0f - 2.0f / (e + 1.0f);
}
// butterfly-merge: keep the half matching this lane's bit, add partner's other half
__device__ __forceinline__ float bfly_merge(float lo, float hi, unsigned bit, int mask) {
    float keep = bit ? hi : lo;
    float send = bit ? lo : hi;
    return keep + __shfl_xor_sync(0xffffffffu, send, mask);
}
// ---- packed fp32 (Blackwell FFMA2) ----
__device__ __forceinline__ u64 ffma2(u64 a, u64 b, u64 c) {
    u64 d;
    asm("fma.rn.f32x2 %0, %1, %2, %3;" : "=l"(d) : "l"(a), "l"(b), "l"(c));
    return d;
}
__device__ __forceinline__ u64 pack2(float x, float y) {
    u64 r;
    asm("mov.b64 %0, {%1, %2};" : "=l"(r) : "f"(x), "f"(y));
    return r;
}
__device__ __forceinline__ float unpack_sum(u64 v) {
    float lo, hi;
    asm("mov.b64 {%0, %1}, %2;" : "=f"(lo), "=f"(hi) : "l"(v));
    return lo + hi;
}

// ---------------- xp0: (B*T,24) @ W_ih0^T -> (B*T,512) + bias ----------------
__global__ __launch_bounds__(256) void xp0_kernel(
    const float* __restrict__ x, const float* __restrict__ Wih,
    const float* __restrict__ bi, const float* __restrict__ bh,
    float* __restrict__ out)
{
    __shared__ float xs[32 * 24];
    int tid = threadIdx.x;
    int r0 = blockIdx.x * 32;
    int h0 = tid * 2;

    float w0[24], w1[24];
    const float4* wp0 = (const float4*)(Wih + (size_t)h0 * 24);
    #pragma unroll
    for (int i = 0; i < 6; i++) {
        float4 v = wp0[i];
        w0[4*i] = v.x; w0[4*i+1] = v.y; w0[4*i+2] = v.z; w0[4*i+3] = v.w;
    }
    const float4* wp1 = (const float4*)(Wih + (size_t)(h0 + 1) * 24);
    #pragma unroll
    for (int i = 0; i < 6; i++) {
        float4 v = wp1[i];
        w1[4*i] = v.x; w1[4*i+1] = v.y; w1[4*i+2] = v.z; w1[4*i+3] = v.w;
    }
    float bias0 = bi[h0] + bh[h0];
    float bias1 = bi[h0 + 1] + bh[h0 + 1];

    for (int i = tid; i < 32 * 24; i += 256) xs[i] = x[(size_t)r0 * 24 + i];
    __syncthreads();

    #pragma unroll 4
    for (int rr = 0; rr < 32; rr++) {
        float a0 = bias0, a1 = bias1;
        #pragma unroll
        for (int f = 0; f < 24; f++) {
            float xv = xs[rr * 24 + f];
            a0 = fmaf(w0[f], xv, a0);
            a1 = fmaf(w1[f], xv, a1);
        }
        *(float2*)(out + (size_t)(r0 + rr) * HID + h0) = make_float2(a0, a1);
    }
}

// ---------------- SGEMM: C[r][j] = bias[j] + sum_k A[r][k]*W[j][k] ----------------
#define GBM 128
#define GBN 128
#define GBK 16
__global__ __launch_bounds__(256, 2) void sgemm_kernel(
    const float* __restrict__ A, const float* __restrict__ W,
    const float* __restrict__ bi, const float* __restrict__ bh,
    float* __restrict__ C)
{
    __shared__ __align__(16) float As[2][GBK][GBM + 4];
    __shared__ __align__(16) float Ws[2][GBK][GBN + 4];

    int tid = threadIdx.x;
    int r0 = blockIdx.y * GBM;
    int j0 = blockIdx.x * GBN;
    int tx = tid & 15, ty = tid >> 4;

    float4 ra[2], rw[2];
    float acc[8][8];
    #pragma unroll
    for (int j = 0; j < 8; j++) {
        int jj = j0 + tx * 8 + j;
        float bj = bi[jj] + bh[jj];
        #pragma unroll
        for (int i = 0; i < 8; i++) acc[i][j] = bj;
    }

    #pragma unroll
    for (int l = 0; l < 2; l++) {
        int idx = tid + l * 256;
        int r = idx >> 2, kq = idx & 3;
        ra[l] = *(const float4*)(A + (size_t)(r0 + r) * HID + kq * 4);
        rw[l] = *(const float4*)(W + (size_t)(j0 + r) * HID + kq * 4);
    }
    #pragma unroll
    for (int l = 0; l < 2; l++) {
        int idx = tid + l * 256;
        int r = idx >> 2, kq = idx & 3;
        As[0][kq*4+0][r] = ra[l].x; As[0][kq*4+1][r] = ra[l].y;
        As[0][kq*4+2][r] = ra[l].z; As[0][kq*4+3][r] = ra[l].w;
        Ws[0][kq*4+0][r] = rw[l].x; Ws[0][kq*4+1][r] = rw[l].y;
        Ws[0][kq*4+2][r] = rw[l].z; Ws[0][kq*4+3][r] = rw[l].w;
    }
    __syncthreads();

    for (int kt = 0; kt < HID / GBK; kt++) {
        int buf = kt & 1;
        if (kt + 1 < HID / GBK) {
            int kbase = (kt + 1) * GBK;
            #pragma unroll
            for (int l = 0; l < 2; l++) {
                int idx = tid + l * 256;
                int r = idx >> 2, kq = idx & 3;
                ra[l] = *(const float4*)(A + (size_t)(r0 + r) * HID + kbase + kq * 4);
                rw[l] = *(const float4*)(W + (size_t)(j0 + r) * HID + kbase + kq * 4);
            }
        }
        #pragma unroll
        for (int k = 0; k < GBK; k++) {
            float4 a0 = *(const float4*)&As[buf][k][ty * 8];
            float4 a1 = *(const float4*)&As[buf][k][ty * 8 + 4];
            float4 b0 = *(const float4*)&Ws[buf][k][tx * 8];
            float4 b1 = *(const float4*)&Ws[buf][k][tx * 8 + 4];
            float av[8] = {a0.x, a0.y, a0.z, a0.w, a1.x, a1.y, a1.z, a1.w};
            float bv[8] = {b0.x, b0.y, b0.z, b0.w, b1.x, b1.y, b1.z, b1.w};
            #pragma unroll
            for (int i = 0; i < 8; i++)
                #pragma unroll
                for (int j = 0; j < 8; j++)
                    acc[i][j] = fmaf(av[i], bv[j], acc[i][j]);
        }
        if (kt + 1 < HID / GBK) {
            int nb = buf ^ 1;
            #pragma unroll
            for (int l = 0; l < 2; l++) {
                int idx = tid + l * 256;
                int r = idx >> 2, kq = idx & 3;
                As[nb][kq*4+0][r] = ra[l].x; As[nb][kq*4+1][r] = ra[l].y;
                As[nb][kq*4+2][r] = ra[l].z; As[nb][kq*4+3][r] = ra[l].w;
                Ws[nb][kq*4+0][r] = rw[l].x; Ws[nb][kq*4+1][r] = rw[l].y;
                Ws[nb][kq*4+2][r] = rw[l].z; Ws[nb][kq*4+3][r] = rw[l].w;
            }
        }
        __syncthreads();
    }

    #pragma unroll
    for (int i = 0; i < 8; i++) {
        int row = r0 + ty * 8 + i;
        float4 o0 = make_float4(acc[i][0], acc[i][1], acc[i][2], acc[i][3]);
        float4 o1 = make_float4(acc[i][4], acc[i][5], acc[i][6], acc[i][7]);
        *(float4*)(C + (size_t)row * HID + j0 + tx * 8)     = o0;
        *(float4*)(C + (size_t)row * HID + j0 + tx * 8 + 4) = o1;
    }
}

// ---------------- recurrence: bulk-copy exchange, region-rotated h layout ----------------
// Fixes R16's layout bugs. Per batch (128 f4): region q in f4 [16q,16q+16)
// holds k in [64q,64q+64); within region, slot_eff = (s + q) & 15 with
// s = 2m + (i&1) + 8*(i>>1) holding k-local = 16m + 4i + {0..3}.
//  - lane l (q=l>>2, m=l&3) reads ONLY region q: 4 x LDS.128 at rotated
//    offsets; bank-quads (s+q) mod 8 distinct per 8-lane phase -> conflict-free
//  - crank's 64 rows = region crank = contiguous 256B -> bulk-copy friendly
//  - exchange: STS into own region, __syncthreads + fence.proxy.async, then
//    threads 0..63 issue ONE 256B cp.async.bulk each (rank=tid&7, batch=tid>>3),
//    complete_tx on receiver's mbar (16KB/phase). 4096 msgs -> 64 msgs.
__global__ __launch_bounds__(512, 1) __cluster_dims__(8, 1, 1)
void rnn_kernel(float* __restrict__ xp, const float* __restrict__ Whh, int T,
                int writeAll)
{
    __shared__ __align__(16) float4 hs4[3][8][128];   // [buf][batch][region layout]
    __shared__ __align__(8) unsigned long long mbars[3];

    int tid = threadIdx.x;
    int w = tid >> 5, l = tid & 31;
    uint32_t crank = ctarank();
    int b0 = (blockIdx.x >> 3) * 8;

    // W tile rows crank*64 + 4w + m, k = 16l + .. ; packed as f32x2 pairs
    u64 w2[4][8];
    #pragma unroll
    for (int m = 0; m < 4; m++) {
        const float4* wp = (const float4*)(Whh +
            (size_t)(crank * 64 + w * 4 + m) * HID + l * 16);
        #pragma unroll
        for (int i = 0; i < 4; i++) {
            float4 v = wp[i];
            w2[m][2*i]   = pack2(v.x, v.y);
            w2[m][2*i+1] = pack2(v.z, v.w);
        }
    }

    unsigned bit4 = (l >> 4) & 1;
    unsigned bit3 = (l >> 3) & 1;
    int bout = ((l >> 2) & 3) | ((l >> 4) << 2);   // batch this lane owns
    int jg   = (int)crank * 64 + w * 4 + (l & 3);  // row this lane owns

    // reader geometry: q = region, rotated slot offsets for i = 0..3
    int q = l >> 2, m_r = l & 3;
    int rbase = 2 * m_r + q;
    int roff[4];
    roff[0] = 16 * q + ((rbase + 0) & 15);
    roff[1] = 16 * q + ((rbase + 1) & 15);
    roff[2] = 16 * q + ((rbase + 8) & 15);
    roff[3] = 16 * q + ((rbase + 9) & 15);

    // writer geometry: this thread's float slot inside buffer (own region crank)
    int sw = 2 * (w >> 2) + (w & 1) + 8 * ((w >> 1) & 1);
    int slot_w = (sw + (int)crank) & 15;
    int wr_off = bout * 512 + (int)crank * 64 + slot_w * 4 + (l & 3); // floats

    const uint32_t BUF = (uint32_t)(8 * 128 * 16);     // 16384 B per h buffer
    uint32_t hsbase = smem_u32(&hs4[0][0][0]);

    uint32_t mbv0 = smem_u32(&mbars[0]);
    uint32_t mbv1 = smem_u32(&mbars[1]);
    uint32_t mbv2 = smem_u32(&mbars[2]);

    if (tid == 0) { mbar_init(mbv0, 1); mbar_init(mbv1, 1); mbar_init(mbv2, 1); }

    // h_{-1} = 0 (all 3 buffers)
    for (int i = tid; i < 3 * 8 * 128; i += 512)
        ((float4*)hs4)[i] = make_float4(0.f, 0.f, 0.f, 0.f);
    __syncthreads();
    if (tid == 0) {  // first-phase expects, posted before any remote delivery
        mbar_expect(mbv0, 16384u);
        mbar_expect(mbv1, 16384u);
        mbar_expect(mbv2, 16384u);
    }
    cluster_sync_all();   // mbarriers + zeroed state visible cluster-wide

    // bulk-copy geometry for threads 0..63: dst rank rr, batch bb
    int rr = tid & 7, bb = tid >> 3;          // valid when tid < 64
    uint32_t sliceoff = (uint32_t)(bb * 2048 + (int)crank * 256);

    // xp value this thread's output needs, prefetched one step ahead
    float xcur = xp[((size_t)(b0 + bout) * T + 0) * HID + jg];

    for (int t = 0; t < T; t++) {
        int rb = t % 3;
        int wb = rb + 1 == 3 ? 0 : rb + 1;
        uint32_t mbr = rb == 0 ? mbv0 : (rb == 1 ? mbv1 : mbv2);
        uint32_t mbw = wb == 0 ? mbv0 : (wb == 1 ? mbv1 : mbv2);

        if (t > 0) {
            uint32_t par = (uint32_t)((t / 3 + (rb == 0 ? 1 : 0)) & 1);
            mbar_wait(mbr, par);
            if (tid == 0) mbar_expect(mbr, 16384u);
        }

        // prefetch next xp (hides under the matvec)
        int tn = (t + 1 < T) ? t + 1 : t;
        float xnext = xp[((size_t)(b0 + bout) * T + tn) * HID + jg];

        // ---- FFMA2 matvec + progressive butterfly reduce ----
        const float4* hbuf = &hs4[rb][0][0];
        float v8[8];
        #pragma unroll
        for (int pair = 0; pair < 2; pair++) {
            float a16[8];
            #pragma unroll
            for (int e = 0; e < 2; e++) {
                int bp = pair + 2 * e;
                const float4* h0f = hbuf + bp * 128;
                const float4* h1f = hbuf + (bp + 4) * 128;
                u64 p0[4], p1[4];
                #pragma unroll
                for (int m = 0; m < 4; m++) { p0[m] = 0ULL; p1[m] = 0ULL; }
                #pragma unroll
                for (int i = 0; i < 4; i++) {
                    ulonglong2 hv0 = *(const ulonglong2*)(h0f + roff[i]);
                    ulonglong2 hv1 = *(const ulonglong2*)(h1f + roff[i]);
                    #pragma unroll
                    for (int m = 0; m < 4; m++) {
                        p0[m] = ffma2(w2[m][2*i],   hv0.x, p0[m]);
                        p0[m] = ffma2(w2[m][2*i+1], hv0.y, p0[m]);
                        p1[m] = ffma2(w2[m][2*i],   hv1.x, p1[m]);
                        p1[m] = ffma2(w2[m][2*i+1], hv1.y, p1[m]);
                    }
                }
                #pragma unroll
                for (int m = 0; m < 4; m++)
                    a16[e * 4 + m] = bfly_merge(unpack_sum(p0[m]),
                                                unpack_sum(p1[m]), bit4, 16);
            }
            #pragma unroll
            for (int m = 0; m < 4; m++)
                v8[pair * 4 + m] = bfly_merge(a16[m], a16[4 + m], bit3, 8);
        }
        float r4[4];
        { unsigned b2 = (l >> 2) & 1;
          #pragma unroll
          for (int qq = 0; qq < 4; qq++) r4[qq] = bfly_merge(v8[qq], v8[4 + qq], b2, 4); }
        float r2[2];
        { unsigned b1 = (l >> 1) & 1;
          #pragma unroll
          for (int qq = 0; qq < 2; qq++) r2[qq] = bfly_merge(r4[qq], r4[2 + qq], b1, 2); }
        float r1 = bfly_merge(r2[0], r2[1], l & 1, 1);

        float hnew = my_tanh(xcur + r1);

        // ys write (off the signaling path)
        if (writeAll || t == T - 1)
            xp[((size_t)(b0 + bout) * T + t) * HID + jg] = hnew;

        if (t + 1 < T) {
            // local store into OUR region of buffer wb (interleaved+rotated slot)
            ((float*)hs4)[wb * 4096 + wr_off] = hnew;
            __syncthreads();            // region complete before bulk reads it
            if (tid < 64) {
                fence_proxy_async_shared();   // STS visible to async proxy
                uint32_t src = hsbase + (uint32_t)wb * BUF + sliceoff;
                bulk_copy_cluster(mapa_u32(src, (uint32_t)rr), src, 256u,
                                  mapa_u32(mbw, (uint32_t)rr));
            }
        }

        xcur = xnext;
    }

    cluster_sync_all();   // no CTA exits while peers' copies may be in flight
}

// ---------------- head: last = ys2[:,T-1,:]; silu(last@W1^T+b1)@W2^T+b2 ----------------
__global__ __launch_bounds__(256) void head_kernel(
    const float* __restrict__ ys, const float* __restrict__ W1,
    const float* __restrict__ b1, const float* __restrict__ W2,
    const float* __restrict__ b2, float* __restrict__ out)
{
    __shared__ float hrow[HID];
    __shared__ float z[1024];
    int b = blockIdx.x;
    int tid = threadIdx.x, w = tid >> 5, l = tid & 31;

    const float* src = ys + ((size_t)b * TT + (TT - 1)) * HID;
    for (int i = tid; i < HID; i += 256) hrow[i] = src[i];
    __syncthreads();

    for (int m = w; m < 1024; m += 8) {
        const float4* wr = (const float4*)(W1 + (size_t)m * HID);
        float a = 0.0f;
        #pragma unroll
        for (int i = 0; i < 4; i++) {
            float4 wv = wr[l + 32 * i];
            float4 hv = *(const float4*)&hrow[4 * (l + 32 * i)];
            a = fmaf(wv.x, hv.x, a); a = fmaf(wv.y, hv.y, a);
            a = fmaf(wv.z, hv.z, a); a = fmaf(wv.w, hv.w, a);
        }
        a += __shfl_xor_sync(0xffffffffu, a, 16);
        a += __shfl_xor_sync(0xffffffffu, a, 8);
        a += __shfl_xor_sync(0xffffffffu, a, 4);
        a += __shfl_xor_sync(0xffffffffu, a, 2);
        a += __shfl_xor_sync(0xffffffffu, a, 1);
        if (l == 0) {
            float zz = a + b1[m];
            z[m] = zz / (1.0f + __expf(-zz));   // silu
        }
    }
    __syncthreads();

    {
        const float4* wr = (const float4*)(W2 + (size_t)w * 1024);
        float a = 0.0f;
        #pragma unroll
        for (int i = 0; i < 8; i++) {
            float4 wv = wr[l + 32 * i];
            float4 zv = *(const float4*)&z[4 * (l + 32 * i)];
            a = fmaf(wv.x, zv.x, a); a = fmaf(wv.y, zv.y, a);
            a = fmaf(wv.z, zv.z, a); a = fmaf(wv.w, zv.w, a);
        }
        a += __shfl_xor_sync(0xffffffffu, a, 16);
        a += __shfl_xor_sync(0xffffffffu, a, 8);
        a += __shfl_xor_sync(0xffffffffu, a, 4);
        a += __shfl_xor_sync(0xffffffffu, a, 2);
        a += __shfl_xor_sync(0xffffffffu, a, 1);
        if (l == 0) out[b * 8 + w] = a + b2[w];
    }
}

// ---------------- launch ----------------
extern "C" void kernel_launch(void* const* d_in, const int* in_sizes, int n_in,
                              void* d_out, int out_size) {
    const float* x     = (const float*)d_in[0];
    const float* Wih0  = (const float*)d_in[1];
    const float* Whh0  = (const float*)d_in[2];
    const float* bih0  = (const float*)d_in[3];
    const float* bhh0  = (const float*)d_in[4];
    const float* Wih1  = (const float*)d_in[5];
    const float* Whh1  = (const float*)d_in[6];
    const float* bih1  = (const float*)d_in[7];
    const float* bhh1  = (const float*)d_in[8];
    const float* Wih2  = (const float*)d_in[9];
    const float* Whh2  = (const float*)d_in[10];
    const float* bih2  = (const float*)d_in[11];
    const float* bhh2  = (const float*)d_in[12];
    const float* W1    = (const float*)d_in[13];
    const float* b1    = (const float*)d_in[14];
    const float* W2    = (const float*)d_in[15];
    const float* b2    = (const float*)d_in[16];
    float* out = (float*)d_out;

    float* bufA; cudaGetSymbolAddress((void**)&bufA, g_bufA);
    float* bufB; cudaGetSymbolAddress((void**)&bufB, g_bufB);

    // layer 0: xp0 then recurrence in place
    xp0_kernel<<<RTOT / 32, 256>>>(x, Wih0, bih0, bhh0, bufA);
    rnn_kernel<<<128, 512>>>(bufA, Whh0, TT, 1);

    // layer 1
    sgemm_kernel<<<dim3(HID / GBN, RTOT / GBM), 256>>>(bufA, Wih1, bih1, bhh1, bufB);
    rnn_kernel<<<128, 512>>>(bufB, Whh1, TT, 1);

    // layer 2 (only the last timestep of ys is consumed by the head)
    sgemm_kernel<<<dim3(HID / GBN, RTOT / GBM), 256>>>(bufB, Wih2, bih2, bhh2, bufA);
    rnn_kernel<<<128, 512>>>(bufA, Whh2, TT, 0);

    // head
    head_kernel<<<NB, 256>>>(bufA, W1, b1, W2, b2, out);
}